// round 2
// baseline (speedup 1.0000x reference)
#include <cuda_runtime.h>
#include <math.h>

#define BB 8192
#define TT 96
#define FF 64
#define HH 256
#define K3 768
#define TB 16
#define TBP 18          // padded row stride (floats): 8B-aligned, low bank conflict
#define NPAIR (TB/2)

// Persistent recurrence state (device globals: allocation-free)
__device__ float g_h[BB * HH];
__device__ float g_prev[BB];

// ---- packed f32x2 helpers (sm_100+) ----
__device__ __forceinline__ unsigned long long pack2dup(float v) {
    unsigned long long r;
    asm("mov.b64 %0, {%1, %1};" : "=l"(r) : "f"(v));
    return r;
}
__device__ __forceinline__ void unpack2(unsigned long long v, float& lo, float& hi) {
    asm("mov.b64 {%0, %1}, %2;" : "=f"(lo), "=f"(hi) : "l"(v));
}
__device__ __forceinline__ void fma2(unsigned long long& d, unsigned long long a,
                                     unsigned long long b) {
    asm("fma.rn.f32x2 %0, %1, %2, %0;" : "+l"(d) : "l"(a), "l"(b));
}

__device__ __forceinline__ float sigmoidf_(float x) {
    return 1.0f / (1.0f + __expf(-x));
}

__global__ void init_kernel(const float* __restrict__ init_state,
                            const float* __restrict__ init_inp) {
    int i = blockIdx.x * blockDim.x + threadIdx.x;
    if (i < BB * HH) g_h[i] = init_state[i];
    if (i < BB) g_prev[i] = init_inp[i];
}

__global__ __launch_bounds__(256, 2) void step_kernel(
    const float* __restrict__ feat,   // [B,T,F]
    const float* __restrict__ Kw,     // [65, 768]
    const float* __restrict__ Rw,     // [256, 768]
    const float* __restrict__ ib,     // [768]
    const float* __restrict__ rb,     // [768]
    const float* __restrict__ dw,     // [256]
    const float* __restrict__ db,     // [1]
    float* __restrict__ out,          // [B,T]
    int t) {
    __shared__ __align__(16) float s_x[FF + 1][TBP];
    __shared__ __align__(16) float s_h[HH][TBP];

    const int j = threadIdx.x;        // hidden column 0..255
    const int b0 = blockIdx.x * TB;   // batch tile start

    // Load h tile transposed: s_h[k][b] = h[b0+b][k]. Global coalesced over j.
#pragma unroll
    for (int b = 0; b < TB; b++)
        s_h[j][b] = g_h[(size_t)(b0 + b) * HH + j];

    if (j < TB) s_x[0][j] = g_prev[b0 + j];
    for (int idx = j; idx < TB * FF; idx += 256) {
        int b = idx / FF, f = idx % FF;
        s_x[1 + f][b] = feat[((size_t)(b0 + b) * TT + t) * FF + f];
    }
    __syncthreads();

    unsigned long long az[NPAIR], ar[NPAIR], ahx[NPAIR], ahh[NPAIR];
#pragma unroll
    for (int p = 0; p < NPAIR; p++) { az[p] = ar[p] = ahx[p] = ahh[p] = 0ULL; }

    // ---------- x phase: k = 0..64 over [prev_out, feat] ----------
    {
        const float* wp = Kw + j;
        float nwz = wp[0], nwr = wp[HH], nwh = wp[2 * HH];
#pragma unroll 1
        for (int k = 0; k < FF + 1; k++) {
            float cwz = nwz, cwr = nwr, cwh = nwh;
            if (k + 1 < FF + 1) {             // prefetch next weight row
                const float* np = Kw + (k + 1) * K3 + j;
                nwz = np[0]; nwr = np[HH]; nwh = np[2 * HH];
            }
            unsigned long long wz = pack2dup(cwz);
            unsigned long long wr = pack2dup(cwr);
            unsigned long long wh = pack2dup(cwh);
#pragma unroll
            for (int p = 0; p < NPAIR; p++) {
                unsigned long long xv =
                    *reinterpret_cast<const unsigned long long*>(&s_x[k][2 * p]);
                fma2(az[p], xv, wz);
                fma2(ar[p], xv, wr);
                fma2(ahx[p], xv, wh);
            }
        }
    }

    // ---------- h phase: k = 0..255 over hidden state ----------
    {
        const float* wp = Rw + j;
        float nwz = wp[0], nwr = wp[HH], nwh = wp[2 * HH];
#pragma unroll 1
        for (int k = 0; k < HH; k++) {
            float cwz = nwz, cwr = nwr, cwh = nwh;
            if (k + 1 < HH) {
                const float* np = Rw + (k + 1) * K3 + j;
                nwz = np[0]; nwr = np[HH]; nwh = np[2 * HH];
            }
            unsigned long long wz = pack2dup(cwz);
            unsigned long long wr = pack2dup(cwr);
            unsigned long long wh = pack2dup(cwh);
#pragma unroll
            for (int p = 0; p < NPAIR; p++) {
                unsigned long long hv =
                    *reinterpret_cast<const unsigned long long*>(&s_h[k][2 * p]);
                fma2(az[p], hv, wz);
                fma2(ar[p], hv, wr);
                fma2(ahh[p], hv, wh);
            }
        }
    }

    const float biz = ib[j] + rb[j];
    const float bir = ib[HH + j] + rb[HH + j];
    const float bhx = ib[2 * HH + j];
    const float bhh = rb[2 * HH + j];
    const float dwj = dw[j];

    float hnew[TB];
#pragma unroll
    for (int p = 0; p < NPAIR; p++) {
        float z0, z1, r0, r1, cx0, cx1, ch0, ch1;
        unpack2(az[p], z0, z1);
        unpack2(ar[p], r0, r1);
        unpack2(ahx[p], cx0, cx1);
        unpack2(ahh[p], ch0, ch1);
        float hold0 = s_h[j][2 * p];
        float hold1 = s_h[j][2 * p + 1];
        float zz0 = sigmoidf_(z0 + biz), zz1 = sigmoidf_(z1 + biz);
        float rr0 = sigmoidf_(r0 + bir), rr1 = sigmoidf_(r1 + bir);
        float c0 = tanhf(cx0 + bhx + rr0 * (ch0 + bhh));
        float c1 = tanhf(cx1 + bhx + rr1 * (ch1 + bhh));
        hnew[2 * p] = zz0 * hold0 + (1.0f - zz0) * c0;
        hnew[2 * p + 1] = zz1 * hold1 + (1.0f - zz1) * c1;
    }

    __syncthreads();  // all reads of s_h done; safe to overwrite
#pragma unroll
    for (int b = 0; b < TB; b++) {
        g_h[(size_t)(b0 + b) * HH + j] = hnew[b];
        s_h[j][b] = hnew[b] * dwj;  // premultiply for dense reduction
    }
    __syncthreads();

    // out[b] = sum_j hnew[b][j]*dw[j] + db ; warp w reduces rows 2w, 2w+1
    const int w = j >> 5, lane = j & 31;
#pragma unroll
    for (int rr = 0; rr < 2; rr++) {
        int b = 2 * w + rr;
        float s = 0.0f;
#pragma unroll
        for (int m = 0; m < HH / 32; m++) s += s_h[lane + 32 * m][b];
#pragma unroll
        for (int off = 16; off; off >>= 1)
            s += __shfl_down_sync(0xffffffffu, s, off);
        if (lane == 0) {
            float v = s + db[0];
            out[(size_t)(b0 + b) * TT + t] = v;
            g_prev[b0 + b] = v;
        }
    }
}

extern "C" void kernel_launch(void* const* d_in, const int* in_sizes, int n_in,
                              void* d_out, int out_size) {
    const float* feat  = (const float*)d_in[0];  // decoder_feature [B,T,F]
    const float* hs0   = (const float*)d_in[1];  // init_state [B,H]
    const float* inp0  = (const float*)d_in[2];  // decoder_init_input [B,1]
    const float* Kw    = (const float*)d_in[3];  // kernel [65,768]
    const float* Rw    = (const float*)d_in[4];  // recurrent_kernel [256,768]
    const float* ibias = (const float*)d_in[5];  // input_bias [768]
    const float* rbias = (const float*)d_in[6];  // recurrent_bias [768]
    const float* dw    = (const float*)d_in[7];  // dense_w [256,1]
    const float* db    = (const float*)d_in[8];  // dense_b [1]
    float* out = (float*)d_out;                  // [B,T,1]

    init_kernel<<<(BB * HH + 255) / 256, 256>>>(hs0, inp0);
    for (int t = 0; t < TT; t++)
        step_kernel<<<BB / TB, 256>>>(feat, Kw, Rw, ibias, rbias, dw, db, out, t);
}

// round 4
// speedup vs baseline: 2.6884x; 2.6884x over previous
#include <cuda_runtime.h>
#include <cuda_bf16.h>
#include <cstdint>

#define BB 8192
#define TT 96
#define FF 64
#define HH 256
#define KTOT 320

// ---------------- static device buffers ----------------
__device__ __align__(256) __nv_bfloat16 g_Bt[2][1024 * KTOT];          // [plane][n*320+k]
__device__ __align__(256) __nv_bfloat16 g_hP[2][2][(size_t)BB * HH];   // [parity][plane]
__device__ __align__(256) __nv_bfloat16 g_fP[2][(size_t)BB * TT * FF]; // [plane]
__device__ float g_prevbuf[3][BB];
__device__ float g_epi[HH * 8];  // {k0z,k0r,k0h,bz,br,bxh,bhh,dw}

// ---------------- helpers ----------------
static __device__ __forceinline__ uint32_t smem_u32(const void* p) {
    uint32_t a;
    asm("{ .reg .u64 t; cvta.to.shared.u64 t, %1; cvt.u32.u64 %0, t; }"
        : "=r"(a) : "l"(p));
    return a;
}
static __device__ __forceinline__ void cpasync16(uint32_t dst, const void* src) {
    asm volatile("cp.async.cg.shared.global [%0], [%1], 16;"
                 :: "r"(dst), "l"(src) : "memory");
}
static __device__ __forceinline__ void ldm4(uint32_t* d, uint32_t a) {
    asm volatile("ldmatrix.sync.aligned.m8n8.x4.shared.b16 {%0,%1,%2,%3}, [%4];"
                 : "=r"(d[0]), "=r"(d[1]), "=r"(d[2]), "=r"(d[3]) : "r"(a));
}
static __device__ __forceinline__ void mmabf(float* c, const uint32_t* a,
                                             const uint32_t* b) {
    asm volatile(
        "mma.sync.aligned.m16n8k16.row.col.f32.bf16.bf16.f32 "
        "{%0,%1,%2,%3},{%4,%5,%6,%7},{%8,%9},{%0,%1,%2,%3};"
        : "+f"(c[0]), "+f"(c[1]), "+f"(c[2]), "+f"(c[3])
        : "r"(a[0]), "r"(a[1]), "r"(a[2]), "r"(a[3]), "r"(b[0]), "r"(b[1]));
}
__device__ __forceinline__ float sigf(float x) {
    return __fdividef(1.0f, 1.0f + __expf(-x));
}
__device__ __forceinline__ float tanhfast(float x) {
    return 1.0f - __fdividef(2.0f, __expf(2.0f * x) + 1.0f);
}
__device__ __forceinline__ float bfpart(uint32_t w, int hi) {
    unsigned short u = hi ? (unsigned short)(w >> 16) : (unsigned short)(w & 0xffff);
    return __bfloat162float(__ushort_as_bfloat16(u));
}

// ---------------- prep kernels ----------------
__global__ void prep_feat(const float* __restrict__ f) {
    size_t i = (size_t)blockIdx.x * 256 + threadIdx.x;
    if (i >= (size_t)BB * TT * FF) return;
    float v = f[i];
    __nv_bfloat16 h = __float2bfloat16(v);
    g_fP[0][i] = h;
    g_fP[1][i] = __float2bfloat16(v - __bfloat162float(h));
}

__global__ void prep_B(const float* __restrict__ Kw, const float* __restrict__ Rw) {
    int idx = blockIdx.x * 256 + threadIdx.x;
    if (idx >= 1024 * KTOT) return;
    int n = idx / KTOT, k = idx % KTOT;
    int blk = n >> 6, w = n & 63, g = w >> 4, jl = w & 15;
    int j = blk * 16 + jl;
    float v = 0.f;
    if (k < HH) {
        if (g == 0) v = Rw[k * 768 + j];
        else if (g == 1) v = Rw[k * 768 + 256 + j];
        else if (g == 3) v = Rw[k * 768 + 512 + j];
    } else {
        int f = k - HH;
        if (g == 0) v = Kw[(1 + f) * 768 + j];
        else if (g == 1) v = Kw[(1 + f) * 768 + 256 + j];
        else if (g == 2) v = Kw[(1 + f) * 768 + 512 + j];
    }
    __nv_bfloat16 h = __float2bfloat16(v);
    g_Bt[0][idx] = h;
    g_Bt[1][idx] = __float2bfloat16(v - __bfloat162float(h));
}

__global__ void prep_init(const float* __restrict__ hs0, const float* __restrict__ inp0,
                          const float* __restrict__ Kw, const float* __restrict__ ib,
                          const float* __restrict__ rb, const float* __restrict__ dw,
                          const float* __restrict__ db) {
    size_t i = (size_t)blockIdx.x * 256 + threadIdx.x;
    if (i < (size_t)BB * HH) {
        float v = hs0[i];
        __nv_bfloat16 h = __float2bfloat16(v);
        g_hP[0][0][i] = h;
        g_hP[0][1][i] = __float2bfloat16(v - __bfloat162float(h));
    }
    if (i < BB) {
        g_prevbuf[0][i] = inp0[i];
        g_prevbuf[1][i] = db[0];
        g_prevbuf[2][i] = db[0];
    }
    if (i < HH) {
        int j = (int)i;
        float* e = &g_epi[j * 8];
        e[0] = Kw[j];
        e[1] = Kw[256 + j];
        e[2] = Kw[512 + j];
        e[3] = ib[j] + rb[j];
        e[4] = ib[256 + j] + rb[256 + j];
        e[5] = ib[512 + j];
        e[6] = rb[512 + j];
        e[7] = dw[j];
    }
}

__global__ void fin_kernel(float* __restrict__ out) {
    int b = blockIdx.x * 256 + threadIdx.x;
    if (b < BB) out[(size_t)b * TT + (TT - 1)] = g_prevbuf[TT % 3][b];
}

// ---------------- step kernel ----------------
// smem: 2 buffers x (Ah 16K | Al 16K | Bh 32K | Bl 32K) + epi 2K
#define BUFSZ 98304
#define EPIOFF (2 * BUFSZ)
#define SMEM_TOTAL (EPIOFF + 2048)

__global__ __launch_bounds__(256, 1) void step_kernel(const float* __restrict__ db,
                                                      float* __restrict__ out, int t) {
    extern __shared__ char sm[];
    const uint32_t smb = smem_u32(sm);
    float* s_epi = (float*)(sm + EPIOFF);

    const int tid = threadIdx.x, lane = tid & 31, wid = tid >> 5;
    const int nt = blockIdx.x, mt = blockIdx.y;
    const int b0 = mt * 128;
    const int rd = t & 1, wr = rd ^ 1;
    const int wm = wid >> 2, wn = wid & 3;
    const int p0 = t % 3, p1 = (t + 1) % 3, p2 = (t + 2) % 3;

    if (nt == 0 && tid < 128) {
        int b = b0 + tid;
        if (t > 0) out[(size_t)b * TT + (t - 1)] = g_prevbuf[p0][b];
        g_prevbuf[p2][b] = db[0];
    }
    for (int i = tid; i < 512; i += 256) s_epi[i] = g_epi[nt * 512 + i];

    // ---- cp.async loader ----
    auto issue = [&](int kc, uint32_t bb) {
#pragma unroll
        for (int i = 0; i < 8; i++) {  // A: 128 rows x 8 chunks x 2 planes
            int idx = tid + i * 256;
            int plane = idx >> 10, rem = idx & 1023, r = rem >> 3, c = rem & 7;
            uint32_t dst = bb + (plane ? 16384u : 0u) + r * 128 + ((c ^ (r & 7)) << 4);
            const __nv_bfloat16* src;
            if (kc < 4)
                src = &g_hP[rd][plane][(size_t)(b0 + r) * HH + kc * 64 + c * 8];
            else
                src = &g_fP[plane][((size_t)(b0 + r) * TT + t) * FF + c * 8];
            cpasync16(dst, src);
        }
#pragma unroll
        for (int i = 0; i < 16; i++) {  // B: 256 rows x 8 chunks x 2 planes
            int idx = tid + i * 256;
            int plane = idx >> 11, rem = idx & 2047, r = rem >> 3, c = rem & 7;
            uint32_t dst = bb + 32768u + (plane ? 32768u : 0u) + r * 128 +
                           ((c ^ (r & 7)) << 4);
            cpasync16(dst, &g_Bt[plane][(size_t)(nt * 256 + r) * KTOT + kc * 64 + c * 8]);
        }
        asm volatile("cp.async.commit_group;" ::: "memory");
    };

    float acc[4][8][4];
#pragma unroll
    for (int mi = 0; mi < 4; mi++)
#pragma unroll
        for (int a = 0; a < 8; a++)
#pragma unroll
            for (int q = 0; q < 4; q++) acc[mi][a][q] = 0.f;

    issue(0, smb);

    // per-lane ldmatrix row components
    const int arow = wm * 64 + (lane & 15), asel = lane >> 4;
    const int bsub = lane >> 3, bl8 = lane & 7;
    const int brow0 = wn * 64 + ((bsub >> 1) << 3) + bl8, bsel = bsub & 1;

    for (int kc = 0; kc < 5; ++kc) {
        const uint32_t bb = smb + (uint32_t)(kc & 1) * BUFSZ;
        if (kc < 4) {
            issue(kc + 1, smb + (uint32_t)((kc + 1) & 1) * BUFSZ);
            asm volatile("cp.async.wait_group 1;" ::: "memory");
        } else {
            asm volatile("cp.async.wait_group 0;" ::: "memory");
        }
        __syncthreads();

        const bool last = (kc == 4);
#pragma unroll
        for (int q = 0; q < 4; q++) {
            uint32_t afr[2][4][4];
#pragma unroll
            for (int pl = 0; pl < 2; pl++)
#pragma unroll
                for (int mi = 0; mi < 4; mi++) {
                    int r = arow + mi * 16;
                    int c = q * 2 + asel;
                    ldm4(afr[pl][mi],
                         bb + (pl ? 16384u : 0u) + r * 128 + ((c ^ (r & 7)) << 4));
                }
            uint32_t bfr[2][8][2];
#pragma unroll
            for (int pl = 0; pl < 2; pl++)
#pragma unroll
                for (int p = 0; p < 4; p++) {
                    if (last ? (p == 3) : (p == 2)) continue;
                    int r = brow0 + p * 16;
                    int c = q * 2 + bsel;
                    uint32_t v[4];
                    ldm4(v, bb + 32768u + (pl ? 32768u : 0u) + r * 128 +
                                ((c ^ (r & 7)) << 4));
                    bfr[pl][2 * p][0] = v[0];
                    bfr[pl][2 * p][1] = v[1];
                    bfr[pl][2 * p + 1][0] = v[2];
                    bfr[pl][2 * p + 1][1] = v[3];
                }
#pragma unroll
            for (int mi = 0; mi < 4; mi++)
#pragma unroll
                for (int a = 0; a < 8; a++) {
                    if (last ? (a >= 6) : (a == 4 || a == 5)) continue;
                    mmabf(acc[mi][a], afr[0][mi], bfr[0][a]);
                    mmabf(acc[mi][a], afr[0][mi], bfr[1][a]);
                    mmabf(acc[mi][a], afr[1][mi], bfr[0][a]);
                }
        }
        __syncthreads();
    }

    // ---- fused epilogue ----
    const int tq = lane & 3, tr = lane >> 2;
    const int jb = (nt * 4 + wn) * 16;
    float ep[2][2][8];
#pragma unroll
    for (int ah = 0; ah < 2; ah++)
#pragma unroll
        for (int i = 0; i < 2; i++) {
            int jl = wn * 16 + ah * 8 + 2 * tq + i;  // index within CTA's 64 j
            float4 u0 = *(const float4*)&s_epi[jl * 8];
            float4 u1 = *(const float4*)&s_epi[jl * 8 + 4];
            ep[ah][i][0] = u0.x; ep[ah][i][1] = u0.y;
            ep[ah][i][2] = u0.z; ep[ah][i][3] = u0.w;
            ep[ah][i][4] = u1.x; ep[ah][i][5] = u1.y;
            ep[ah][i][6] = u1.z; ep[ah][i][7] = u1.w;
        }

#pragma unroll
    for (int mi = 0; mi < 4; mi++)
#pragma unroll
        for (int rs = 0; rs < 2; rs++) {
            const int b = b0 + wm * 64 + mi * 16 + tr + rs * 8;
            const float prev = g_prevbuf[p0][b];
            float dacc = 0.f;
#pragma unroll
            for (int ah = 0; ah < 2; ah++) {
                const int j0 = jb + ah * 8 + 2 * tq;
                uint32_t hw = *(const uint32_t*)&g_hP[rd][0][(size_t)b * HH + j0];
                uint32_t lw = *(const uint32_t*)&g_hP[rd][1][(size_t)b * HH + j0];
                float hn2[2];
#pragma unroll
                for (int i = 0; i < 2; i++) {
                    const float* e = ep[ah][i];
                    float cz = acc[mi][0 + ah][rs * 2 + i] + prev * e[0] + e[3];
                    float cr = acc[mi][2 + ah][rs * 2 + i] + prev * e[1] + e[4];
                    float cx = acc[mi][4 + ah][rs * 2 + i] + prev * e[2] + e[5];
                    float ch = acc[mi][6 + ah][rs * 2 + i] + e[6];
                    float z = sigf(cz), r = sigf(cr);
                    float cand = tanhfast(cx + r * ch);
                    float hold = bfpart(hw, i) + bfpart(lw, i);
                    float hn = z * hold + (1.f - z) * cand;
                    dacc += hn * e[7];
                    hn2[i] = hn;
                }
                __nv_bfloat16 h0 = __float2bfloat16(hn2[0]);
                __nv_bfloat16 h1 = __float2bfloat16(hn2[1]);
                __nv_bfloat16 l0 = __float2bfloat16(hn2[0] - __bfloat162float(h0));
                __nv_bfloat16 l1 = __float2bfloat16(hn2[1] - __bfloat162float(h1));
                uint32_t uhi = (uint32_t)__bfloat16_as_ushort(h0) |
                               ((uint32_t)__bfloat16_as_ushort(h1) << 16);
                uint32_t ulo = (uint32_t)__bfloat16_as_ushort(l0) |
                               ((uint32_t)__bfloat16_as_ushort(l1) << 16);
                *(uint32_t*)&g_hP[wr][0][(size_t)b * HH + j0] = uhi;
                *(uint32_t*)&g_hP[wr][1][(size_t)b * HH + j0] = ulo;
            }
            dacc += __shfl_xor_sync(0xffffffffu, dacc, 1);
            dacc += __shfl_xor_sync(0xffffffffu, dacc, 2);
            if (tq == 0) atomicAdd(&g_prevbuf[p1][b], dacc);
        }
}

// ---------------- launch ----------------
extern "C" void kernel_launch(void* const* d_in, const int* in_sizes, int n_in,
                              void* d_out, int out_size) {
    const float* feat  = (const float*)d_in[0];
    const float* hs0   = (const float*)d_in[1];
    const float* inp0  = (const float*)d_in[2];
    const float* Kw    = (const float*)d_in[3];
    const float* Rw    = (const float*)d_in[4];
    const float* ibias = (const float*)d_in[5];
    const float* rbias = (const float*)d_in[6];
    const float* dw    = (const float*)d_in[7];
    const float* db    = (const float*)d_in[8];
    float* out = (float*)d_out;

    cudaFuncSetAttribute(step_kernel, cudaFuncAttributeMaxDynamicSharedMemorySize,
                         SMEM_TOTAL);

    size_t nf = (size_t)BB * TT * FF;
    prep_feat<<<(unsigned)((nf + 255) / 256), 256>>>(feat);
    prep_B<<<(1024 * KTOT + 255) / 256, 256>>>(Kw, Rw);
    prep_init<<<(BB * HH + 255) / 256, 256>>>(hs0, inp0, Kw, ibias, rbias, dw, db);

    dim3 grid(4, 64);
    for (int t = 0; t < TT; ++t)
        step_kernel<<<grid, 256, SMEM_TOTAL>>>(db, out, t);

    fin_kernel<<<(BB + 255) / 256, 256>>>(out);
}

// round 5
// speedup vs baseline: 3.3458x; 1.2445x over previous
#include <cuda_runtime.h>
#include <cuda_fp16.h>
#include <cstdint>

#define BB 8192
#define TT 96
#define FF 64
#define HH 256
#define KTOT 320

// ---------------- static device buffers ----------------
__device__ __align__(256) __half g_Bt[2][1024 * KTOT];           // [hi/lo][n*320+k]
__device__ __align__(256) __half g_hP[2][2][(size_t)BB * HH];    // [parity][hi/lo]
__device__ __align__(256) __half g_f16[(size_t)BB * TT * FF];    // features (hi only)
__device__ float g_prevbuf[3][BB];
__device__ float g_epi[HH * 8];  // {k0z,k0r,k0h,bz,br,bxh,bhh,dw}

// ---------------- helpers ----------------
static __device__ __forceinline__ uint32_t smem_u32(const void* p) {
    uint32_t a;
    asm("{ .reg .u64 t; cvta.to.shared.u64 t, %1; cvt.u32.u64 %0, t; }"
        : "=r"(a) : "l"(p));
    return a;
}
static __device__ __forceinline__ void cpasync16(uint32_t dst, const void* src) {
    asm volatile("cp.async.cg.shared.global [%0], [%1], 16;"
                 :: "r"(dst), "l"(src) : "memory");
}
static __device__ __forceinline__ void ldm4(uint32_t* d, uint32_t a) {
    asm volatile("ldmatrix.sync.aligned.m8n8.x4.shared.b16 {%0,%1,%2,%3}, [%4];"
                 : "=r"(d[0]), "=r"(d[1]), "=r"(d[2]), "=r"(d[3]) : "r"(a));
}
static __device__ __forceinline__ void mmaf16(float* c, const uint32_t* a,
                                              const uint32_t* b) {
    asm volatile(
        "mma.sync.aligned.m16n8k16.row.col.f32.f16.f16.f32 "
        "{%0,%1,%2,%3},{%4,%5,%6,%7},{%8,%9},{%0,%1,%2,%3};"
        : "+f"(c[0]), "+f"(c[1]), "+f"(c[2]), "+f"(c[3])
        : "r"(a[0]), "r"(a[1]), "r"(a[2]), "r"(a[3]), "r"(b[0]), "r"(b[1]));
}
__device__ __forceinline__ float sigf(float x) {
    return __fdividef(1.0f, 1.0f + __expf(-x));
}
__device__ __forceinline__ float tanhfast(float x) {
    return 1.0f - __fdividef(2.0f, __expf(2.0f * x) + 1.0f);
}
__device__ __forceinline__ float hfpart(uint32_t w, int hi) {
    __half_raw r;
    r.x = hi ? (unsigned short)(w >> 16) : (unsigned short)(w & 0xffff);
    return __half2float(__half(r));
}

// ---------------- prep kernels ----------------
__global__ void prep_feat(const float* __restrict__ f) {
    size_t i = (size_t)blockIdx.x * 256 + threadIdx.x;
    if (i >= (size_t)BB * TT * FF) return;
    g_f16[i] = __float2half_rn(f[i]);
}

__global__ void prep_B(const float* __restrict__ Kw, const float* __restrict__ Rw) {
    int idx = blockIdx.x * 256 + threadIdx.x;
    if (idx >= 1024 * KTOT) return;
    int n = idx / KTOT, k = idx % KTOT;
    int blk = n >> 6, w = n & 63, g = w >> 4, jl = w & 15;
    int j = blk * 16 + jl;
    float v = 0.f;
    if (k < HH) {
        if (g == 0) v = Rw[k * 768 + j];
        else if (g == 1) v = Rw[k * 768 + 256 + j];
        else if (g == 3) v = Rw[k * 768 + 512 + j];
    } else {
        int f = k - HH;
        if (g == 0) v = Kw[(1 + f) * 768 + j];
        else if (g == 1) v = Kw[(1 + f) * 768 + 256 + j];
        else if (g == 2) v = Kw[(1 + f) * 768 + 512 + j];
    }
    __half h = __float2half_rn(v);
    g_Bt[0][idx] = h;
    g_Bt[1][idx] = __float2half_rn(v - __half2float(h));
}

__global__ void prep_init(const float* __restrict__ hs0, const float* __restrict__ inp0,
                          const float* __restrict__ Kw, const float* __restrict__ ib,
                          const float* __restrict__ rb, const float* __restrict__ dw,
                          const float* __restrict__ db) {
    size_t i = (size_t)blockIdx.x * 256 + threadIdx.x;
    if (i < (size_t)BB * HH) {
        float v = hs0[i];
        __half h = __float2half_rn(v);
        g_hP[0][0][i] = h;
        g_hP[0][1][i] = __float2half_rn(v - __half2float(h));
    }
    if (i < BB) {
        g_prevbuf[0][i] = inp0[i];
        g_prevbuf[1][i] = db[0];
        g_prevbuf[2][i] = db[0];
    }
    if (i < HH) {
        int j = (int)i;
        float* e = &g_epi[j * 8];
        e[0] = Kw[j];
        e[1] = Kw[256 + j];
        e[2] = Kw[512 + j];
        e[3] = ib[j] + rb[j];
        e[4] = ib[256 + j] + rb[256 + j];
        e[5] = ib[512 + j];
        e[6] = rb[512 + j];
        e[7] = dw[j];
    }
}

__global__ void fin_kernel(float* __restrict__ out) {
    int b = blockIdx.x * 256 + threadIdx.x;
    if (b < BB) out[(size_t)b * TT + (TT - 1)] = g_prevbuf[TT % 3][b];
}

// ---------------- step kernel ----------------
// smem buffer: A 16K (1 plane) | Bh 32K | Bl 32K  = 80K, double buffered
#define BUFSZ 81920
#define BOFF 16384
#define EPIOFF (2 * BUFSZ)
#define SMEM_TOTAL (EPIOFF + 2048)

__global__ __launch_bounds__(256, 1) void step_kernel(const float* __restrict__ db,
                                                      float* __restrict__ out, int t) {
    extern __shared__ char sm[];
    const uint32_t smb = smem_u32(sm);
    float* s_epi = (float*)(sm + EPIOFF);

    const int tid = threadIdx.x, lane = tid & 31, wid = tid >> 5;
    const int nt = blockIdx.x, mt = blockIdx.y;
    const int b0 = mt * 128;
    const int rd = t & 1, wr = rd ^ 1;
    const int wm = wid >> 2, wn = wid & 3;
    const int p0 = t % 3, p1 = (t + 1) % 3, p2 = (t + 2) % 3;

    if (nt == 0 && tid < 128) {
        int b = b0 + tid;
        if (t > 0) out[(size_t)b * TT + (t - 1)] = g_prevbuf[p0][b];
        g_prevbuf[p2][b] = db[0];
    }
    for (int i = tid; i < 512; i += 256) s_epi[i] = g_epi[nt * 512 + i];

    // ---- cp.async loader ----
    auto issue = [&](int kc, uint32_t bb) {
#pragma unroll
        for (int i = 0; i < 4; i++) {  // A (hi only): 128 rows x 8 chunks
            int idx = tid + i * 256;
            int r = idx >> 3, c = idx & 7;
            uint32_t dst = bb + r * 128 + ((c ^ (r & 7)) << 4);
            const __half* src;
            if (kc < 4)
                src = &g_hP[rd][0][(size_t)(b0 + r) * HH + kc * 64 + c * 8];
            else
                src = &g_f16[((size_t)(b0 + r) * TT + t) * FF + c * 8];
            cpasync16(dst, src);
        }
#pragma unroll
        for (int i = 0; i < 16; i++) {  // B: 2 planes x 256 rows x 8 chunks
            int idx = tid + i * 256;
            int plane = idx >> 11, rem = idx & 2047, r = rem >> 3, c = rem & 7;
            uint32_t dst = bb + BOFF + (plane ? 32768u : 0u) + r * 128 +
                           ((c ^ (r & 7)) << 4);
            cpasync16(dst, &g_Bt[plane][(size_t)(nt * 256 + r) * KTOT + kc * 64 + c * 8]);
        }
        asm volatile("cp.async.commit_group;" ::: "memory");
    };

    float acc[4][8][4];
#pragma unroll
    for (int mi = 0; mi < 4; mi++)
#pragma unroll
        for (int a = 0; a < 8; a++)
#pragma unroll
            for (int q = 0; q < 4; q++) acc[mi][a][q] = 0.f;

    issue(0, smb);

    const int arow = wm * 64 + (lane & 15), asel = lane >> 4;
    const int bsub = lane >> 3, bl8 = lane & 7;
    const int brow0 = wn * 64 + ((bsub >> 1) << 3) + bl8, bsel = bsub & 1;

    for (int kc = 0; kc < 5; ++kc) {
        const uint32_t bb = smb + (uint32_t)(kc & 1) * BUFSZ;
        if (kc < 4) {
            issue(kc + 1, smb + (uint32_t)((kc + 1) & 1) * BUFSZ);
            asm volatile("cp.async.wait_group 1;" ::: "memory");
        } else {
            asm volatile("cp.async.wait_group 0;" ::: "memory");
        }
        __syncthreads();

        const bool last = (kc == 4);
#pragma unroll
        for (int q = 0; q < 4; q++) {
            uint32_t afr[4][4];
#pragma unroll
            for (int mi = 0; mi < 4; mi++) {
                int r = arow + mi * 16;
                int c = q * 2 + asel;
                ldm4(afr[mi], bb + r * 128 + ((c ^ (r & 7)) << 4));
            }
            uint32_t bfr[2][8][2];
#pragma unroll
            for (int pl = 0; pl < 2; pl++)
#pragma unroll
                for (int p = 0; p < 4; p++) {
                    if (last ? (p == 3) : (p == 2)) continue;
                    int r = brow0 + p * 16;
                    int c = q * 2 + bsel;
                    uint32_t v[4];
                    ldm4(v, bb + BOFF + (pl ? 32768u : 0u) + r * 128 +
                                ((c ^ (r & 7)) << 4));
                    bfr[pl][2 * p][0] = v[0];
                    bfr[pl][2 * p][1] = v[1];
                    bfr[pl][2 * p + 1][0] = v[2];
                    bfr[pl][2 * p + 1][1] = v[3];
                }
#pragma unroll
            for (int mi = 0; mi < 4; mi++)
#pragma unroll
                for (int a = 0; a < 8; a++) {
                    if (last ? (a >= 6) : (a == 4 || a == 5)) continue;
                    mmaf16(acc[mi][a], afr[mi], bfr[0][a]);
                    mmaf16(acc[mi][a], afr[mi], bfr[1][a]);
                }
        }
        __syncthreads();
    }

    // ---- fused epilogue ----
    const int tq = lane & 3, tr = lane >> 2;
    const int jb = (nt * 4 + wn) * 16;
    float ep[2][2][8];
#pragma unroll
    for (int ah = 0; ah < 2; ah++)
#pragma unroll
        for (int i = 0; i < 2; i++) {
            int jl = wn * 16 + ah * 8 + 2 * tq + i;
            float4 u0 = *(const float4*)&s_epi[jl * 8];
            float4 u1 = *(const float4*)&s_epi[jl * 8 + 4];
            ep[ah][i][0] = u0.x; ep[ah][i][1] = u0.y;
            ep[ah][i][2] = u0.z; ep[ah][i][3] = u0.w;
            ep[ah][i][4] = u1.x; ep[ah][i][5] = u1.y;
            ep[ah][i][6] = u1.z; ep[ah][i][7] = u1.w;
        }

#pragma unroll
    for (int mi = 0; mi < 4; mi++)
#pragma unroll
        for (int rs = 0; rs < 2; rs++) {
            const int b = b0 + wm * 64 + mi * 16 + tr + rs * 8;
            const float prev = g_prevbuf[p0][b];
            float dacc = 0.f;
#pragma unroll
            for (int ah = 0; ah < 2; ah++) {
                const int j0 = jb + ah * 8 + 2 * tq;
                uint32_t hw = *(const uint32_t*)&g_hP[rd][0][(size_t)b * HH + j0];
                uint32_t lw = *(const uint32_t*)&g_hP[rd][1][(size_t)b * HH + j0];
                float hn2[2];
#pragma unroll
                for (int i = 0; i < 2; i++) {
                    const float* e = ep[ah][i];
                    float cz = acc[mi][0 + ah][rs * 2 + i] + prev * e[0] + e[3];
                    float cr = acc[mi][2 + ah][rs * 2 + i] + prev * e[1] + e[4];
                    float cx = acc[mi][4 + ah][rs * 2 + i] + prev * e[2] + e[5];
                    float ch = acc[mi][6 + ah][rs * 2 + i] + e[6];
                    float z = sigf(cz), r = sigf(cr);
                    float cand = tanhfast(cx + r * ch);
                    float hold = hfpart(hw, i) + hfpart(lw, i);
                    float hn = z * hold + (1.f - z) * cand;
                    dacc += hn * e[7];
                    hn2[i] = hn;
                }
                __half h0 = __float2half_rn(hn2[0]);
                __half h1 = __float2half_rn(hn2[1]);
                __half l0 = __float2half_rn(hn2[0] - __half2float(h0));
                __half l1 = __float2half_rn(hn2[1] - __half2float(h1));
                uint32_t uhi = (uint32_t)__half_as_ushort(h0) |
                               ((uint32_t)__half_as_ushort(h1) << 16);
                uint32_t ulo = (uint32_t)__half_as_ushort(l0) |
                               ((uint32_t)__half_as_ushort(l1) << 16);
                *(uint32_t*)&g_hP[wr][0][(size_t)b * HH + j0] = uhi;
                *(uint32_t*)&g_hP[wr][1][(size_t)b * HH + j0] = ulo;
            }
            dacc += __shfl_xor_sync(0xffffffffu, dacc, 1);
            dacc += __shfl_xor_sync(0xffffffffu, dacc, 2);
            if (tq == 0) atomicAdd(&g_prevbuf[p1][b], dacc);
        }
}

// ---------------- launch ----------------
extern "C" void kernel_launch(void* const* d_in, const int* in_sizes, int n_in,
                              void* d_out, int out_size) {
    const float* feat  = (const float*)d_in[0];
    const float* hs0   = (const float*)d_in[1];
    const float* inp0  = (const float*)d_in[2];
    const float* Kw    = (const float*)d_in[3];
    const float* Rw    = (const float*)d_in[4];
    const float* ibias = (const float*)d_in[5];
    const float* rbias = (const float*)d_in[6];
    const float* dw    = (const float*)d_in[7];
    const float* db    = (const float*)d_in[8];
    float* out = (float*)d_out;

    cudaFuncSetAttribute(step_kernel, cudaFuncAttributeMaxDynamicSharedMemorySize,
                         SMEM_TOTAL);

    size_t nf = (size_t)BB * TT * FF;
    prep_feat<<<(unsigned)((nf + 255) / 256), 256>>>(feat);
    prep_B<<<(1024 * KTOT + 255) / 256, 256>>>(Kw, Rw);
    prep_init<<<(BB * HH + 255) / 256, 256>>>(hs0, inp0, Kw, ibias, rbias, dw, db);

    dim3 grid(4, 64);
    for (int t = 0; t < TT; ++t)
        step_kernel<<<grid, 256, SMEM_TOTAL>>>(db, out, t);

    fin_kernel<<<(BB + 255) / 256, 256>>>(out);
}

// round 6
// speedup vs baseline: 3.9513x; 1.1810x over previous
#include <cuda_runtime.h>
#include <cuda_fp16.h>
#include <cstdint>

#define BB 8192
#define TT 96
#define FF 64
#define HH 256
#define KTOT 320

// ---------------- static device buffers ----------------
__device__ __align__(256) __half g_Bt[2][1024 * KTOT];           // [hi/lo][n*320+k]
__device__ __align__(256) __half g_hP[2][2][(size_t)BB * HH];    // [parity][hi/lo]
__device__ __align__(256) __half g_f16[(size_t)BB * TT * FF];    // features (hi only)
__device__ float g_prevbuf[3][BB];
__device__ float g_epi[HH * 8];  // {k0z,k0r,k0h,bz,br,bxh,bhh,dw}

// ---------------- helpers ----------------
static __device__ __forceinline__ uint32_t smem_u32(const void* p) {
    uint32_t a;
    asm("{ .reg .u64 t; cvta.to.shared.u64 t, %1; cvt.u32.u64 %0, t; }"
        : "=r"(a) : "l"(p));
    return a;
}
static __device__ __forceinline__ void cpasync16(uint32_t dst, const void* src) {
    asm volatile("cp.async.cg.shared.global [%0], [%1], 16;"
                 :: "r"(dst), "l"(src) : "memory");
}
static __device__ __forceinline__ void ldm4(uint32_t* d, uint32_t a) {
    asm volatile("ldmatrix.sync.aligned.m8n8.x4.shared.b16 {%0,%1,%2,%3}, [%4];"
                 : "=r"(d[0]), "=r"(d[1]), "=r"(d[2]), "=r"(d[3]) : "r"(a));
}
static __device__ __forceinline__ void mmaf16(float* c, const uint32_t* a,
                                              uint32_t b0, uint32_t b1) {
    asm volatile(
        "mma.sync.aligned.m16n8k16.row.col.f32.f16.f16.f32 "
        "{%0,%1,%2,%3},{%4,%5,%6,%7},{%8,%9},{%0,%1,%2,%3};"
        : "+f"(c[0]), "+f"(c[1]), "+f"(c[2]), "+f"(c[3])
        : "r"(a[0]), "r"(a[1]), "r"(a[2]), "r"(a[3]), "r"(b0), "r"(b1));
}
__device__ __forceinline__ float sigf(float x) {
    return __fdividef(1.0f, 1.0f + __expf(-x));
}
__device__ __forceinline__ float tanhfast(float x) {
    return 1.0f - __fdividef(2.0f, __expf(2.0f * x) + 1.0f);
}
__device__ __forceinline__ float hfpart(uint32_t w, int hi) {
    __half_raw r;
    r.x = hi ? (unsigned short)(w >> 16) : (unsigned short)(w & 0xffff);
    return __half2float(__half(r));
}

// ---------------- prep kernels ----------------
__global__ void prep_feat(const float* __restrict__ f) {
    size_t i = (size_t)blockIdx.x * 256 + threadIdx.x;
    if (i >= (size_t)BB * TT * FF) return;
    g_f16[i] = __float2half_rn(f[i]);
}

__global__ void prep_B(const float* __restrict__ Kw, const float* __restrict__ Rw) {
    int idx = blockIdx.x * 256 + threadIdx.x;
    if (idx >= 1024 * KTOT) return;
    int n = idx / KTOT, k = idx % KTOT;
    int blk = n >> 6, w = n & 63, g = w >> 4, jl = w & 15;
    int j = blk * 16 + jl;
    float v = 0.f;
    if (k < HH) {
        if (g == 0) v = Rw[k * 768 + j];
        else if (g == 1) v = Rw[k * 768 + 256 + j];
        else if (g == 3) v = Rw[k * 768 + 512 + j];
    } else {
        int f = k - HH;
        if (g == 0) v = Kw[(1 + f) * 768 + j];
        else if (g == 1) v = Kw[(1 + f) * 768 + 256 + j];
        else if (g == 2) v = Kw[(1 + f) * 768 + 512 + j];
    }
    __half h = __float2half_rn(v);
    g_Bt[0][idx] = h;
    g_Bt[1][idx] = __float2half_rn(v - __half2float(h));
}

__global__ void prep_init(const float* __restrict__ hs0, const float* __restrict__ inp0,
                          const float* __restrict__ Kw, const float* __restrict__ ib,
                          const float* __restrict__ rb, const float* __restrict__ dw,
                          const float* __restrict__ db) {
    size_t i = (size_t)blockIdx.x * 256 + threadIdx.x;
    if (i < (size_t)BB * HH) {
        float v = hs0[i];
        __half h = __float2half_rn(v);
        g_hP[0][0][i] = h;
        g_hP[0][1][i] = __float2half_rn(v - __half2float(h));
    }
    if (i < BB) {
        g_prevbuf[0][i] = inp0[i];
        g_prevbuf[1][i] = db[0];
        g_prevbuf[2][i] = db[0];
    }
    if (i < HH) {
        int j = (int)i;
        float* e = &g_epi[j * 8];
        e[0] = Kw[j];
        e[1] = Kw[256 + j];
        e[2] = Kw[512 + j];
        e[3] = ib[j] + rb[j];
        e[4] = ib[256 + j] + rb[256 + j];
        e[5] = ib[512 + j];
        e[6] = rb[512 + j];
        e[7] = dw[j];
    }
}

__global__ void fin_kernel(float* __restrict__ out) {
    int b = blockIdx.x * 256 + threadIdx.x;
    if (b < BB) out[(size_t)b * TT + (TT - 1)] = g_prevbuf[TT % 3][b];
}

// ---------------- step kernel ----------------
// smem per buffer: A 16K | Bh 16K | Bl 16K = 48K; double buffered + 1K epi
#define BUFSZ 49152
#define BOFF 16384
#define EPIOFF (2 * BUFSZ)
#define SMEM_TOTAL (EPIOFF + 1024)

__global__ __launch_bounds__(256, 2) void step_kernel(const float* __restrict__ db,
                                                      float* __restrict__ out, int t) {
    extern __shared__ char sm[];
    const uint32_t smb = smem_u32(sm);
    float* s_epi = (float*)(sm + EPIOFF);

    const int tid = threadIdx.x, lane = tid & 31, wid = tid >> 5;
    const int nt = blockIdx.x, mt = blockIdx.y;
    const int b0 = mt * 128;
    const int rd = t & 1, wr = rd ^ 1;
    const int wm = wid >> 1, wn = wid & 1;   // warp tile: 32m x 64n
    const int p0 = t % 3, p1 = (t + 1) % 3, p2 = (t + 2) % 3;

    if (nt == 0 && tid < 128) {
        int b = b0 + tid;
        if (t > 0) out[(size_t)b * TT + (t - 1)] = g_prevbuf[p0][b];
        g_prevbuf[p2][b] = db[0];
    }
    if (tid < 256) s_epi[tid] = g_epi[nt * 256 + tid];

    // ---- cp.async loader ----
    auto issue = [&](int kc, uint32_t bb) {
#pragma unroll
        for (int i = 0; i < 4; i++) {  // A (hi only): 128 rows x 8 chunks
            int idx = tid + i * 256;
            int r = idx >> 3, c = idx & 7;
            uint32_t dst = bb + r * 128 + ((c ^ (r & 7)) << 4);
            const __half* src;
            if (kc < 4)
                src = &g_hP[rd][0][(size_t)(b0 + r) * HH + kc * 64 + c * 8];
            else
                src = &g_f16[((size_t)(b0 + r) * TT + t) * FF + c * 8];
            cpasync16(dst, src);
        }
#pragma unroll
        for (int i = 0; i < 8; i++) {  // B: 2 planes x 128 rows x 8 chunks
            int idx = tid + i * 256;
            int plane = idx >> 10, rem = idx & 1023, r = rem >> 3, c = rem & 7;
            uint32_t dst = bb + BOFF + (plane ? 16384u : 0u) + r * 128 +
                           ((c ^ (r & 7)) << 4);
            cpasync16(dst, &g_Bt[plane][(size_t)(nt * 128 + r) * KTOT + kc * 64 + c * 8]);
        }
        asm volatile("cp.async.commit_group;" ::: "memory");
    };

    float acc[2][8][4];
#pragma unroll
    for (int mi = 0; mi < 2; mi++)
#pragma unroll
        for (int a = 0; a < 8; a++)
#pragma unroll
            for (int q = 0; q < 4; q++) acc[mi][a][q] = 0.f;

    issue(0, smb);

    const int arow = wm * 32 + (lane & 15), asel = lane >> 4;
    const int bsub = lane >> 3, bl8 = lane & 7;
    const int brow0 = wn * 64 + ((bsub >> 1) << 3) + bl8, bsel = bsub & 1;

    for (int kc = 0; kc < 5; ++kc) {
        const uint32_t bb = smb + (uint32_t)(kc & 1) * BUFSZ;
        if (kc < 4) {
            issue(kc + 1, smb + (uint32_t)((kc + 1) & 1) * BUFSZ);
            asm volatile("cp.async.wait_group 1;" ::: "memory");
        } else {
            asm volatile("cp.async.wait_group 0;" ::: "memory");
        }
        __syncthreads();

        const bool last = (kc == 4);
#pragma unroll
        for (int q = 0; q < 4; q++) {
            uint32_t afr[2][4];
#pragma unroll
            for (int mi = 0; mi < 2; mi++) {
                int r = arow + mi * 16;
                int c = q * 2 + asel;
                ldm4(afr[mi], bb + r * 128 + ((c ^ (r & 7)) << 4));
            }
#pragma unroll
            for (int pl = 0; pl < 2; pl++)
#pragma unroll
                for (int p = 0; p < 4; p++) {
                    if (last ? (p == 3) : (p == 2)) continue;
                    int r = brow0 + p * 16;
                    int c = q * 2 + bsel;
                    uint32_t v[4];
                    ldm4(v, bb + BOFF + (pl ? 16384u : 0u) + r * 128 +
                                ((c ^ (r & 7)) << 4));
                    mmaf16(acc[0][2 * p], afr[0], v[0], v[1]);
                    mmaf16(acc[0][2 * p + 1], afr[0], v[2], v[3]);
                    mmaf16(acc[1][2 * p], afr[1], v[0], v[1]);
                    mmaf16(acc[1][2 * p + 1], afr[1], v[2], v[3]);
                }
        }
        __syncthreads();
    }

    // ---- fused epilogue ----
    const int tq = lane & 3, tr = lane >> 2;
    const int jb = (nt * 2 + wn) * 16;
    float ep[2][2][8];
#pragma unroll
    for (int ah = 0; ah < 2; ah++)
#pragma unroll
        for (int i = 0; i < 2; i++) {
            int jl = wn * 16 + ah * 8 + 2 * tq + i;  // within CTA's 32 j
            float4 u0 = *(const float4*)&s_epi[jl * 8];
            float4 u1 = *(const float4*)&s_epi[jl * 8 + 4];
            ep[ah][i][0] = u0.x; ep[ah][i][1] = u0.y;
            ep[ah][i][2] = u0.z; ep[ah][i][3] = u0.w;
            ep[ah][i][4] = u1.x; ep[ah][i][5] = u1.y;
            ep[ah][i][6] = u1.z; ep[ah][i][7] = u1.w;
        }

#pragma unroll
    for (int mi = 0; mi < 2; mi++)
#pragma unroll
        for (int rs = 0; rs < 2; rs++) {
            const int b = b0 + wm * 32 + mi * 16 + tr + rs * 8;
            const float prev = g_prevbuf[p0][b];
            float dacc = 0.f;
#pragma unroll
            for (int ah = 0; ah < 2; ah++) {
                const int j0 = jb + ah * 8 + 2 * tq;
                uint32_t hw = *(const uint32_t*)&g_hP[rd][0][(size_t)b * HH + j0];
                uint32_t lw = *(const uint32_t*)&g_hP[rd][1][(size_t)b * HH + j0];
                float hn2[2];
#pragma unroll
                for (int i = 0; i < 2; i++) {
                    const float* e = ep[ah][i];
                    float cz = acc[mi][0 + ah][rs * 2 + i] + prev * e[0] + e[3];
                    float cr = acc[mi][2 + ah][rs * 2 + i] + prev * e[1] + e[4];
                    float cx = acc[mi][4 + ah][rs * 2 + i] + prev * e[2] + e[5];
                    float ch = acc[mi][6 + ah][rs * 2 + i] + e[6];
                    float z = sigf(cz), r = sigf(cr);
                    float cand = tanhfast(cx + r * ch);
                    float hold = hfpart(hw, i) + hfpart(lw, i);
                    float hn = z * hold + (1.f - z) * cand;
                    dacc += hn * e[7];
                    hn2[i] = hn;
                }
                __half h0 = __float2half_rn(hn2[0]);
                __half h1 = __float2half_rn(hn2[1]);
                __half l0 = __float2half_rn(hn2[0] - __half2float(h0));
                __half l1 = __float2half_rn(hn2[1] - __half2float(h1));
                uint32_t uhi = (uint32_t)__half_as_ushort(h0) |
                               ((uint32_t)__half_as_ushort(h1) << 16);
                uint32_t ulo = (uint32_t)__half_as_ushort(l0) |
                               ((uint32_t)__half_as_ushort(l1) << 16);
                *(uint32_t*)&g_hP[wr][0][(size_t)b * HH + j0] = uhi;
                *(uint32_t*)&g_hP[wr][1][(size_t)b * HH + j0] = ulo;
            }
            dacc += __shfl_xor_sync(0xffffffffu, dacc, 1);
            dacc += __shfl_xor_sync(0xffffffffu, dacc, 2);
            if (tq == 0) atomicAdd(&g_prevbuf[p1][b], dacc);
        }
}

// ---------------- launch ----------------
extern "C" void kernel_launch(void* const* d_in, const int* in_sizes, int n_in,
                              void* d_out, int out_size) {
    const float* feat  = (const float*)d_in[0];
    const float* hs0   = (const float*)d_in[1];
    const float* inp0  = (const float*)d_in[2];
    const float* Kw    = (const float*)d_in[3];
    const float* Rw    = (const float*)d_in[4];
    const float* ibias = (const float*)d_in[5];
    const float* rbias = (const float*)d_in[6];
    const float* dw    = (const float*)d_in[7];
    const float* db    = (const float*)d_in[8];
    float* out = (float*)d_out;

    cudaFuncSetAttribute(step_kernel, cudaFuncAttributeMaxDynamicSharedMemorySize,
                         SMEM_TOTAL);

    size_t nf = (size_t)BB * TT * FF;
    prep_feat<<<(unsigned)((nf + 255) / 256), 256>>>(feat);
    prep_B<<<(1024 * KTOT + 255) / 256, 256>>>(Kw, Rw);
    prep_init<<<(BB * HH + 255) / 256, 256>>>(hs0, inp0, Kw, ibias, rbias, dw, db);

    dim3 grid(8, 64);
    for (int t = 0; t < TT; ++t)
        step_kernel<<<grid, 256, SMEM_TOTAL>>>(db, out, t);

    fin_kernel<<<(BB + 255) / 256, 256>>>(out);
}

// round 7
// speedup vs baseline: 5.6950x; 1.4413x over previous
#include <cuda_runtime.h>
#include <cuda_fp16.h>
#include <cstdint>

#define BB 8192
#define TT 96
#define FF 64
#define HH 256
#define KTOT 320

// ---------------- static device buffers ----------------
__device__ __align__(256) __half g_Bt[1024 * KTOT];              // weights hi [n*320+k]
__device__ __align__(256) __half g_hP[2][2][(size_t)BB * HH];    // [parity][hi/lo]
__device__ __align__(256) __half g_f16[(size_t)BB * TT * FF];    // features (hi only)
__device__ float g_prevbuf[3][BB];
__device__ float g_epi[HH * 8];  // {k0z,k0r,k0h,bz,br,bxh,bhh,dw}

// ---------------- helpers ----------------
static __device__ __forceinline__ uint32_t smem_u32(const void* p) {
    uint32_t a;
    asm("{ .reg .u64 t; cvta.to.shared.u64 t, %1; cvt.u32.u64 %0, t; }"
        : "=r"(a) : "l"(p));
    return a;
}
static __device__ __forceinline__ void cpasync16(uint32_t dst, const void* src) {
    asm volatile("cp.async.cg.shared.global [%0], [%1], 16;"
                 :: "r"(dst), "l"(src) : "memory");
}
static __device__ __forceinline__ void ldm4(uint32_t* d, uint32_t a) {
    asm volatile("ldmatrix.sync.aligned.m8n8.x4.shared.b16 {%0,%1,%2,%3}, [%4];"
                 : "=r"(d[0]), "=r"(d[1]), "=r"(d[2]), "=r"(d[3]) : "r"(a));
}
static __device__ __forceinline__ void mmaf16(float* c, const uint32_t* a,
                                              uint32_t b0, uint32_t b1) {
    asm volatile(
        "mma.sync.aligned.m16n8k16.row.col.f32.f16.f16.f32 "
        "{%0,%1,%2,%3},{%4,%5,%6,%7},{%8,%9},{%0,%1,%2,%3};"
        : "+f"(c[0]), "+f"(c[1]), "+f"(c[2]), "+f"(c[3])
        : "r"(a[0]), "r"(a[1]), "r"(a[2]), "r"(a[3]), "r"(b0), "r"(b1));
}
__device__ __forceinline__ float sigf(float x) {
    return __fdividef(1.0f, 1.0f + __expf(-x));
}
__device__ __forceinline__ float tanhfast(float x) {
    return 1.0f - __fdividef(2.0f, __expf(2.0f * x) + 1.0f);
}
__device__ __forceinline__ float hfpart(uint32_t w, int hi) {
    __half_raw r;
    r.x = hi ? (unsigned short)(w >> 16) : (unsigned short)(w & 0xffff);
    return __half2float(__half(r));
}

// ---------------- prep kernels ----------------
__global__ void prep_feat(const float* __restrict__ f) {
    size_t i = (size_t)blockIdx.x * 256 + threadIdx.x;
    if (i >= (size_t)BB * TT * FF) return;
    g_f16[i] = __float2half_rn(f[i]);
}

__global__ void prep_B(const float* __restrict__ Kw, const float* __restrict__ Rw) {
    int idx = blockIdx.x * 256 + threadIdx.x;
    if (idx >= 1024 * KTOT) return;
    int n = idx / KTOT, k = idx % KTOT;
    int blk = n >> 6, w = n & 63, g = w >> 4, jl = w & 15;
    int j = blk * 16 + jl;
    float v = 0.f;
    if (k < HH) {
        if (g == 0) v = Rw[k * 768 + j];
        else if (g == 1) v = Rw[k * 768 + 256 + j];
        else if (g == 3) v = Rw[k * 768 + 512 + j];
    } else {
        int f = k - HH;
        if (g == 0) v = Kw[(1 + f) * 768 + j];
        else if (g == 1) v = Kw[(1 + f) * 768 + 256 + j];
        else if (g == 2) v = Kw[(1 + f) * 768 + 512 + j];
    }
    g_Bt[idx] = __float2half_rn(v);
}

__global__ void prep_init(const float* __restrict__ hs0, const float* __restrict__ inp0,
                          const float* __restrict__ Kw, const float* __restrict__ ib,
                          const float* __restrict__ rb, const float* __restrict__ dw,
                          const float* __restrict__ db) {
    size_t i = (size_t)blockIdx.x * 256 + threadIdx.x;
    if (i < (size_t)BB * HH) {
        float v = hs0[i];
        __half h = __float2half_rn(v);
        g_hP[0][0][i] = h;
        g_hP[0][1][i] = __float2half_rn(v - __half2float(h));
    }
    if (i < BB) {
        g_prevbuf[0][i] = inp0[i];
        g_prevbuf[1][i] = db[0];
        g_prevbuf[2][i] = db[0];
    }
    if (i < HH) {
        int j = (int)i;
        float* e = &g_epi[j * 8];
        e[0] = Kw[j];
        e[1] = Kw[256 + j];
        e[2] = Kw[512 + j];
        e[3] = ib[j] + rb[j];
        e[4] = ib[256 + j] + rb[256 + j];
        e[5] = ib[512 + j];
        e[6] = rb[512 + j];
        e[7] = dw[j];
    }
}

__global__ void fin_kernel(float* __restrict__ out) {
    int b = blockIdx.x * 256 + threadIdx.x;
    if (b < BB) out[(size_t)b * TT + (TT - 1)] = g_prevbuf[TT % 3][b];
}

// ---------------- step kernel ----------------
// smem per buffer: A 16K | B 16K = 32K; double buffered + 1K epi
#define BUFSZ 32768
#define BOFF 16384
#define EPIOFF (2 * BUFSZ)
#define SMEM_TOTAL (EPIOFF + 1024)

__global__ __launch_bounds__(256, 2) void step_kernel(const float* __restrict__ db,
                                                      float* __restrict__ out, int t) {
    extern __shared__ char sm[];
    const uint32_t smb = smem_u32(sm);
    float* s_epi = (float*)(sm + EPIOFF);

    const int tid = threadIdx.x, lane = tid & 31, wid = tid >> 5;
    const int nt = blockIdx.x, mt = blockIdx.y;
    const int b0 = mt * 128;
    const int rd = t & 1, wr = rd ^ 1;
    const int wm = wid >> 1, wn = wid & 1;   // warp tile: 32m x 64n
    const int p0 = t % 3, p1 = (t + 1) % 3, p2 = (t + 2) % 3;

    if (nt == 0 && tid < 128) {
        int b = b0 + tid;
        if (t > 0) out[(size_t)b * TT + (t - 1)] = g_prevbuf[p0][b];
        g_prevbuf[p2][b] = db[0];
    }
    if (tid < 256) s_epi[tid] = g_epi[nt * 256 + tid];

    // ---- cp.async loader ----
    auto issue = [&](int kc, uint32_t bb) {
#pragma unroll
        for (int i = 0; i < 4; i++) {  // A (hi only): 128 rows x 8 chunks
            int idx = tid + i * 256;
            int r = idx >> 3, c = idx & 7;
            uint32_t dst = bb + r * 128 + ((c ^ (r & 7)) << 4);
            const __half* src;
            if (kc < 4)
                src = &g_hP[rd][0][(size_t)(b0 + r) * HH + kc * 64 + c * 8];
            else
                src = &g_f16[((size_t)(b0 + r) * TT + t) * FF + c * 8];
            cpasync16(dst, src);
        }
#pragma unroll
        for (int i = 0; i < 4; i++) {  // B: 128 rows x 8 chunks
            int idx = tid + i * 256;
            int r = idx >> 3, c = idx & 7;
            uint32_t dst = bb + BOFF + r * 128 + ((c ^ (r & 7)) << 4);
            cpasync16(dst, &g_Bt[(size_t)(nt * 128 + r) * KTOT + kc * 64 + c * 8]);
        }
        asm volatile("cp.async.commit_group;" ::: "memory");
    };

    float acc[2][8][4];
#pragma unroll
    for (int mi = 0; mi < 2; mi++)
#pragma unroll
        for (int a = 0; a < 8; a++)
#pragma unroll
            for (int q = 0; q < 4; q++) acc[mi][a][q] = 0.f;

    issue(0, smb);

    const int arow = wm * 32 + (lane & 15), asel = lane >> 4;
    const int bsub = lane >> 3, bl8 = lane & 7;
    const int brow0 = wn * 64 + ((bsub >> 1) << 3) + bl8, bsel = bsub & 1;

    for (int kc = 0; kc < 5; ++kc) {
        const uint32_t bb = smb + (uint32_t)(kc & 1) * BUFSZ;
        if (kc < 4) {
            issue(kc + 1, smb + (uint32_t)((kc + 1) & 1) * BUFSZ);
            asm volatile("cp.async.wait_group 1;" ::: "memory");
        } else {
            asm volatile("cp.async.wait_group 0;" ::: "memory");
        }
        __syncthreads();

        const bool last = (kc == 4);
#pragma unroll
        for (int q = 0; q < 4; q++) {
            uint32_t afr[2][4];
#pragma unroll
            for (int mi = 0; mi < 2; mi++) {
                int r = arow + mi * 16;
                int c = q * 2 + asel;
                ldm4(afr[mi], bb + r * 128 + ((c ^ (r & 7)) << 4));
            }
#pragma unroll
            for (int p = 0; p < 4; p++) {
                if (last ? (p == 3) : (p == 2)) continue;
                int r = brow0 + p * 16;
                int c = q * 2 + bsel;
                uint32_t v[4];
                ldm4(v, bb + BOFF + r * 128 + ((c ^ (r & 7)) << 4));
                mmaf16(acc[0][2 * p], afr[0], v[0], v[1]);
                mmaf16(acc[0][2 * p + 1], afr[0], v[2], v[3]);
                mmaf16(acc[1][2 * p], afr[1], v[0], v[1]);
                mmaf16(acc[1][2 * p + 1], afr[1], v[2], v[3]);
            }
        }
        __syncthreads();
    }

    // ---- fused epilogue ----
    const int tq = lane & 3, tr = lane >> 2;
    const int jb = (nt * 2 + wn) * 16;
    float ep[2][2][8];
#pragma unroll
    for (int ah = 0; ah < 2; ah++)
#pragma unroll
        for (int i = 0; i < 2; i++) {
            int jl = wn * 16 + ah * 8 + 2 * tq + i;  // within CTA's 32 j
            float4 u0 = *(const float4*)&s_epi[jl * 8];
            float4 u1 = *(const float4*)&s_epi[jl * 8 + 4];
            ep[ah][i][0] = u0.x; ep[ah][i][1] = u0.y;
            ep[ah][i][2] = u0.z; ep[ah][i][3] = u0.w;
            ep[ah][i][4] = u1.x; ep[ah][i][5] = u1.y;
            ep[ah][i][6] = u1.z; ep[ah][i][7] = u1.w;
        }

#pragma unroll
    for (int mi = 0; mi < 2; mi++)
#pragma unroll
        for (int rs = 0; rs < 2; rs++) {
            const int b = b0 + wm * 32 + mi * 16 + tr + rs * 8;
            const float prev = g_prevbuf[p0][b];
            float dacc = 0.f;
#pragma unroll
            for (int ah = 0; ah < 2; ah++) {
                const int j0 = jb + ah * 8 + 2 * tq;
                uint32_t hw = *(const uint32_t*)&g_hP[rd][0][(size_t)b * HH + j0];
                uint32_t lw = *(const uint32_t*)&g_hP[rd][1][(size_t)b * HH + j0];
                float hn2[2];
#pragma unroll
                for (int i = 0; i < 2; i++) {
                    const float* e = ep[ah][i];
                    float cz = acc[mi][0 + ah][rs * 2 + i] + prev * e[0] + e[3];
                    float cr = acc[mi][2 + ah][rs * 2 + i] + prev * e[1] + e[4];
                    float cx = acc[mi][4 + ah][rs * 2 + i] + prev * e[2] + e[5];
                    float ch = acc[mi][6 + ah][rs * 2 + i] + e[6];
                    float z = sigf(cz), r = sigf(cr);
                    float cand = tanhfast(cx + r * ch);
                    float hold = hfpart(hw, i) + hfpart(lw, i);
                    float hn = z * hold + (1.f - z) * cand;
                    dacc += hn * e[7];
                    hn2[i] = hn;
                }
                __half h0 = __float2half_rn(hn2[0]);
                __half h1 = __float2half_rn(hn2[1]);
                __half l0 = __float2half_rn(hn2[0] - __half2float(h0));
                __half l1 = __float2half_rn(hn2[1] - __half2float(h1));
                uint32_t uhi = (uint32_t)__half_as_ushort(h0) |
                               ((uint32_t)__half_as_ushort(h1) << 16);
                uint32_t ulo = (uint32_t)__half_as_ushort(l0) |
                               ((uint32_t)__half_as_ushort(l1) << 16);
                *(uint32_t*)&g_hP[wr][0][(size_t)b * HH + j0] = uhi;
                *(uint32_t*)&g_hP[wr][1][(size_t)b * HH + j0] = ulo;
            }
            dacc += __shfl_xor_sync(0xffffffffu, dacc, 1);
            dacc += __shfl_xor_sync(0xffffffffu, dacc, 2);
            if (tq == 0) atomicAdd(&g_prevbuf[p1][b], dacc);
        }
}

// ---------------- launch ----------------
extern "C" void kernel_launch(void* const* d_in, const int* in_sizes, int n_in,
                              void* d_out, int out_size) {
    const float* feat  = (const float*)d_in[0];
    const float* hs0   = (const float*)d_in[1];
    const float* inp0  = (const float*)d_in[2];
    const float* Kw    = (const float*)d_in[3];
    const float* Rw    = (const float*)d_in[4];
    const float* ibias = (const float*)d_in[5];
    const float* rbias = (const float*)d_in[6];
    const float* dw    = (const float*)d_in[7];
    const float* db    = (const float*)d_in[8];
    float* out = (float*)d_out;

    cudaFuncSetAttribute(step_kernel, cudaFuncAttributeMaxDynamicSharedMemorySize,
                         SMEM_TOTAL);

    size_t nf = (size_t)BB * TT * FF;
    prep_feat<<<(unsigned)((nf + 255) / 256), 256>>>(feat);
    prep_B<<<(1024 * KTOT + 255) / 256, 256>>>(Kw, Rw);
    prep_init<<<(BB * HH + 255) / 256, 256>>>(hs0, inp0, Kw, ibias, rbias, dw, db);

    dim3 grid(8, 64);
    for (int t = 0; t < TT; ++t)
        step_kernel<<<grid, 256, SMEM_TOTAL>>>(db, out, t);

    fin_kernel<<<(BB + 255) / 256, 256>>>(out);
}

// round 8
// speedup vs baseline: 5.7885x; 1.0164x over previous
#include <cuda_runtime.h>
#include <cuda_fp16.h>
#include <cstdint>

#define BB 8192
#define TT 96
#define FF 64
#define HH 256
#define KTOT 320

// ---------------- static device buffers ----------------
__device__ __align__(256) __half g_Bt[1024 * KTOT];              // weights hi [n*320+k]
__device__ __align__(256) __half g_hP[2][2][(size_t)BB * HH];    // [parity][hi/lo]
__device__ __align__(256) __half g_f16[(size_t)BB * TT * FF];    // features (hi only)
__device__ float g_prevbuf[3][BB];
__device__ float g_epi[HH * 8];  // {k0z,k0r,k0h,bz,br,bxh,bhh,dw}

// ---------------- helpers ----------------
static __device__ __forceinline__ uint32_t smem_u32(const void* p) {
    uint32_t a;
    asm("{ .reg .u64 t; cvta.to.shared.u64 t, %1; cvt.u32.u64 %0, t; }"
        : "=r"(a) : "l"(p));
    return a;
}
static __device__ __forceinline__ void cpasync16(uint32_t dst, const void* src) {
    asm volatile("cp.async.cg.shared.global [%0], [%1], 16;"
                 :: "r"(dst), "l"(src) : "memory");
}
static __device__ __forceinline__ void ldm4(uint32_t* d, uint32_t a) {
    asm volatile("ldmatrix.sync.aligned.m8n8.x4.shared.b16 {%0,%1,%2,%3}, [%4];"
                 : "=r"(d[0]), "=r"(d[1]), "=r"(d[2]), "=r"(d[3]) : "r"(a));
}
static __device__ __forceinline__ void mmaf16(float* c, const uint32_t* a,
                                              uint32_t b0, uint32_t b1) {
    asm volatile(
        "mma.sync.aligned.m16n8k16.row.col.f32.f16.f16.f32 "
        "{%0,%1,%2,%3},{%4,%5,%6,%7},{%8,%9},{%0,%1,%2,%3};"
        : "+f"(c[0]), "+f"(c[1]), "+f"(c[2]), "+f"(c[3])
        : "r"(a[0]), "r"(a[1]), "r"(a[2]), "r"(a[3]), "r"(b0), "r"(b1));
}
__device__ __forceinline__ float sigf(float x) {
    return __fdividef(1.0f, 1.0f + __expf(-x));
}
__device__ __forceinline__ float tanhfast(float x) {
    return 1.0f - __fdividef(2.0f, __expf(2.0f * x) + 1.0f);
}
__device__ __forceinline__ float hfpart(uint32_t w, int hi) {
    __half_raw r;
    r.x = hi ? (unsigned short)(w >> 16) : (unsigned short)(w & 0xffff);
    return __half2float(__half(r));
}

// ---------------- prep kernels ----------------
__global__ void prep_feat(const float* __restrict__ f) {
    size_t i = (size_t)blockIdx.x * 256 + threadIdx.x;
    if (i >= (size_t)BB * TT * FF) return;
    g_f16[i] = __float2half_rn(f[i]);
}

__global__ void prep_B(const float* __restrict__ Kw, const float* __restrict__ Rw) {
    int idx = blockIdx.x * 256 + threadIdx.x;
    if (idx >= 1024 * KTOT) return;
    int n = idx / KTOT, k = idx % KTOT;
    int blk = n >> 6, w = n & 63, g = w >> 4, jl = w & 15;
    int j = blk * 16 + jl;
    float v = 0.f;
    if (k < HH) {
        if (g == 0) v = Rw[k * 768 + j];
        else if (g == 1) v = Rw[k * 768 + 256 + j];
        else if (g == 3) v = Rw[k * 768 + 512 + j];
    } else {
        int f = k - HH;
        if (g == 0) v = Kw[(1 + f) * 768 + j];
        else if (g == 1) v = Kw[(1 + f) * 768 + 256 + j];
        else if (g == 2) v = Kw[(1 + f) * 768 + 512 + j];
    }
    g_Bt[idx] = __float2half_rn(v);
}

__global__ void prep_init(const float* __restrict__ hs0, const float* __restrict__ inp0,
                          const float* __restrict__ Kw, const float* __restrict__ ib,
                          const float* __restrict__ rb, const float* __restrict__ dw,
                          const float* __restrict__ db) {
    size_t i = (size_t)blockIdx.x * 256 + threadIdx.x;
    if (i < (size_t)BB * HH) {
        float v = hs0[i];
        __half h = __float2half_rn(v);
        g_hP[0][0][i] = h;
        g_hP[0][1][i] = __float2half_rn(v - __half2float(h));
    }
    if (i < BB) {
        g_prevbuf[0][i] = inp0[i];
        g_prevbuf[1][i] = db[0];
        g_prevbuf[2][i] = db[0];
    }
    if (i < HH) {
        int j = (int)i;
        float* e = &g_epi[j * 8];
        e[0] = Kw[j];
        e[1] = Kw[256 + j];
        e[2] = Kw[512 + j];
        e[3] = ib[j] + rb[j];
        e[4] = ib[256 + j] + rb[256 + j];
        e[5] = ib[512 + j];
        e[6] = rb[512 + j];
        e[7] = dw[j];
    }
}

__global__ void fin_kernel(float* __restrict__ out) {
    int b = blockIdx.x * 256 + threadIdx.x;
    if (b < BB) out[(size_t)b * TT + (TT - 1)] = g_prevbuf[TT % 3][b];
}

// ---------------- step kernel ----------------
// smem: ring of 3 buffers, each A 16K | B 16K = 32K; + 1K epi
#define BUFSZ 32768
#define BOFF 16384
#define EPIOFF (3 * BUFSZ)
#define SMEM_TOTAL (EPIOFF + 1024)

__global__ __launch_bounds__(256, 2) void step_kernel(const float* __restrict__ db,
                                                      float* __restrict__ out, int t) {
    extern __shared__ char sm[];
    const uint32_t smb = smem_u32(sm);
    float* s_epi = (float*)(sm + EPIOFF);

    const int tid = threadIdx.x, lane = tid & 31, wid = tid >> 5;
    const int nt = blockIdx.x, mt = blockIdx.y;
    const int b0 = mt * 128;
    const int rd = t & 1, wr = rd ^ 1;
    const int wm = wid >> 1, wn = wid & 1;   // warp tile: 32m x 64n
    const int p0 = t % 3, p1 = (t + 1) % 3, p2 = (t + 2) % 3;

    // ---- cp.async loader ----
    auto issue = [&](int kc, uint32_t bb) {
#pragma unroll
        for (int i = 0; i < 4; i++) {  // A (hi only): 128 rows x 8 chunks
            int idx = tid + i * 256;
            int r = idx >> 3, c = idx & 7;
            uint32_t dst = bb + r * 128 + ((c ^ (r & 7)) << 4);
            const __half* src;
            if (kc < 4)
                src = &g_hP[rd][0][(size_t)(b0 + r) * HH + kc * 64 + c * 8];
            else
                src = &g_f16[((size_t)(b0 + r) * TT + t) * FF + c * 8];
            cpasync16(dst, src);
        }
#pragma unroll
        for (int i = 0; i < 4; i++) {  // B: 128 rows x 8 chunks
            int idx = tid + i * 256;
            int r = idx >> 3, c = idx & 7;
            uint32_t dst = bb + BOFF + r * 128 + ((c ^ (r & 7)) << 4);
            cpasync16(dst, &g_Bt[(size_t)(nt * 128 + r) * KTOT + kc * 64 + c * 8]);
        }
        asm volatile("cp.async.commit_group;" ::: "memory");
    };

    // front-load the first two chunks before anything else
    issue(0, smb);
    issue(1, smb + BUFSZ);

    if (nt == 0 && tid < 128) {
        int b = b0 + tid;
        if (t > 0) out[(size_t)b * TT + (t - 1)] = g_prevbuf[p0][b];
        g_prevbuf[p2][b] = db[0];
    }
    s_epi[tid] = g_epi[nt * 256 + tid];

    float acc[2][8][4];
#pragma unroll
    for (int mi = 0; mi < 2; mi++)
#pragma unroll
        for (int a = 0; a < 8; a++)
#pragma unroll
            for (int q = 0; q < 4; q++) acc[mi][a][q] = 0.f;

    const int arow = wm * 32 + (lane & 15), asel = lane >> 4;
    const int bsub = lane >> 3, bl8 = lane & 7;
    const int brow0 = wn * 64 + ((bsub >> 1) << 3) + bl8, bsel = bsub & 1;

    for (int kc = 0; kc < 5; ++kc) {
        if (kc < 4)
            asm volatile("cp.async.wait_group 1;" ::: "memory");
        else
            asm volatile("cp.async.wait_group 0;" ::: "memory");
        __syncthreads();  // single barrier per chunk (ring-3 makes reuse safe)

        if (kc < 3) {
            static const uint32_t boffs[3] = {0, BUFSZ, 2 * BUFSZ};
            issue(kc + 2, smb + boffs[(kc + 2) % 3]);
        }

        const uint32_t bb = smb + (uint32_t)(kc % 3) * BUFSZ;
        const bool last = (kc == 4);
#pragma unroll
        for (int q = 0; q < 4; q++) {
            uint32_t afr[2][4];
#pragma unroll
            for (int mi = 0; mi < 2; mi++) {
                int r = arow + mi * 16;
                int c = q * 2 + asel;
                ldm4(afr[mi], bb + r * 128 + ((c ^ (r & 7)) << 4));
            }
#pragma unroll
            for (int p = 0; p < 4; p++) {
                if (last ? (p == 3) : (p == 2)) continue;
                int r = brow0 + p * 16;
                int c = q * 2 + bsel;
                uint32_t v[4];
                ldm4(v, bb + BOFF + r * 128 + ((c ^ (r & 7)) << 4));
                mmaf16(acc[0][2 * p], afr[0], v[0], v[1]);
                mmaf16(acc[0][2 * p + 1], afr[0], v[2], v[3]);
                mmaf16(acc[1][2 * p], afr[1], v[0], v[1]);
                mmaf16(acc[1][2 * p + 1], afr[1], v[2], v[3]);
            }
        }
    }

    // ---- fused epilogue ----
    const int tq = lane & 3, tr = lane >> 2;
    const int jb = (nt * 2 + wn) * 16;
    float ep[2][2][8];
#pragma unroll
    for (int ah = 0; ah < 2; ah++)
#pragma unroll
        for (int i = 0; i < 2; i++) {
            int jl = wn * 16 + ah * 8 + 2 * tq + i;  // within CTA's 32 j
            float4 u0 = *(const float4*)&s_epi[jl * 8];
            float4 u1 = *(const float4*)&s_epi[jl * 8 + 4];
            ep[ah][i][0] = u0.x; ep[ah][i][1] = u0.y;
            ep[ah][i][2] = u0.z; ep[ah][i][3] = u0.w;
            ep[ah][i][4] = u1.x; ep[ah][i][5] = u1.y;
            ep[ah][i][6] = u1.z; ep[ah][i][7] = u1.w;
        }

#pragma unroll
    for (int mi = 0; mi < 2; mi++)
#pragma unroll
        for (int rs = 0; rs < 2; rs++) {
            const int b = b0 + wm * 32 + mi * 16 + tr + rs * 8;
            const float prev = g_prevbuf[p0][b];
            float dacc = 0.f;
#pragma unroll
            for (int ah = 0; ah < 2; ah++) {
                const int j0 = jb + ah * 8 + 2 * tq;
                uint32_t hw = *(const uint32_t*)&g_hP[rd][0][(size_t)b * HH + j0];
                uint32_t lw = *(const uint32_t*)&g_hP[rd][1][(size_t)b * HH + j0];
                float hn2[2];
#pragma unroll
                for (int i = 0; i < 2; i++) {
                    const float* e = ep[ah][i];
                    float cz = acc[mi][0 + ah][rs * 2 + i] + prev * e[0] + e[3];
                    float cr = acc[mi][2 + ah][rs * 2 + i] + prev * e[1] + e[4];
                    float cx = acc[mi][4 + ah][rs * 2 + i] + prev * e[2] + e[5];
                    float ch = acc[mi][6 + ah][rs * 2 + i] + e[6];
                    float z = sigf(cz), r = sigf(cr);
                    float cand = tanhfast(cx + r * ch);
                    float hold = hfpart(hw, i) + hfpart(lw, i);
                    float hn = z * hold + (1.f - z) * cand;
                    dacc += hn * e[7];
                    hn2[i] = hn;
                }
                __half h0 = __float2half_rn(hn2[0]);
                __half h1 = __float2half_rn(hn2[1]);
                __half l0 = __float2half_rn(hn2[0] - __half2float(h0));
                __half l1 = __float2half_rn(hn2[1] - __half2float(h1));
                uint32_t uhi = (uint32_t)__half_as_ushort(h0) |
                               ((uint32_t)__half_as_ushort(h1) << 16);
                uint32_t ulo = (uint32_t)__half_as_ushort(l0) |
                               ((uint32_t)__half_as_ushort(l1) << 16);
                *(uint32_t*)&g_hP[wr][0][(size_t)b * HH + j0] = uhi;
                *(uint32_t*)&g_hP[wr][1][(size_t)b * HH + j0] = ulo;
            }
            dacc += __shfl_xor_sync(0xffffffffu, dacc, 1);
            dacc += __shfl_xor_sync(0xffffffffu, dacc, 2);
            if (tq == 0) atomicAdd(&g_prevbuf[p1][b], dacc);
        }
}

// ---------------- launch ----------------
extern "C" void kernel_launch(void* const* d_in, const int* in_sizes, int n_in,
                              void* d_out, int out_size) {
    const float* feat  = (const float*)d_in[0];
    const float* hs0   = (const float*)d_in[1];
    const float* inp0  = (const float*)d_in[2];
    const float* Kw    = (const float*)d_in[3];
    const float* Rw    = (const float*)d_in[4];
    const float* ibias = (const float*)d_in[5];
    const float* rbias = (const float*)d_in[6];
    const float* dw    = (const float*)d_in[7];
    const float* db    = (const float*)d_in[8];
    float* out = (float*)d_out;

    cudaFuncSetAttribute(step_kernel, cudaFuncAttributeMaxDynamicSharedMemorySize,
                         SMEM_TOTAL);

    size_t nf = (size_t)BB * TT * FF;
    prep_feat<<<(unsigned)((nf + 255) / 256), 256>>>(feat);
    prep_B<<<(1024 * KTOT + 255) / 256, 256>>>(Kw, Rw);
    prep_init<<<(BB * HH + 255) / 256, 256>>>(hs0, inp0, Kw, ibias, rbias, dw, db);

    dim3 grid(8, 64);
    for (int t = 0; t < TT; ++t)
        step_kernel<<<grid, 256, SMEM_TOTAL>>>(db, out, t);

    fin_kernel<<<(BB + 255) / 256, 256>>>(out);
}